// round 5
// baseline (speedup 1.0000x reference)
#include <cuda_runtime.h>
#include <cuda_bf16.h>
#include <math.h>
#include <stdint.h>

// Problem constants
#define NN   20000
#define EE   320000
#define HH   4

// ---------------- scratch (static __device__, no allocs) ----------------
__device__ float g_proj[NN * 1024];    // combined [fs | fd] projections
__device__ float g_A0[NN * 512];       // tf32-rounded, k-permuted n_feat
__device__ float g_h1[NN * 128];       // k-permuted hidden outputs
__device__ float g_h2[NN * 128];
__device__ float g_wbuf[720896];       // tf32-rounded, transposed [N,K], k-permuted weights
__device__ int   g_cnt[NN];
__device__ int   g_cursor[NN];
__device__ int   g_rowptr[NN + 1];
__device__ int   g_csrsrc[EE];

#define OFF_WL0 0
#define OFF_WR0 262144
#define OFF_WL1 524288
#define OFF_WR1 589824
#define OFF_WL2 655360
#define OFF_WR2 688128

__device__ __forceinline__ uint32_t f2tf32(float x) {
    uint32_t r;
    asm("cvt.rna.tf32.f32 %0, %1;" : "=r"(r) : "f"(x));
    return r;
}
__device__ __forceinline__ float tf32r(float x) { return __uint_as_float(f2tf32(x)); }

// k-permutation within 16-groups: thread t's frag k's {t,t+4,t+8,t+12} -> contiguous
__device__ __forceinline__ int permk(int k) {
    return (k & ~15) | ((k & 3) << 2) | ((k >> 2) & 3);
}

// ---------------- A0 prep: tf32 round + column k-permute (row len 512) ----------------
__global__ void prep_a0_kernel(const float* __restrict__ in, float* __restrict__ out, int n) {
    int i = (blockIdx.x * blockDim.x + threadIdx.x) * 4;
    if (i < n) {
        float4 v = *reinterpret_cast<const float4*>(in + i);
        int r = i >> 9, c = i & 511;            // c is 4-aligned
        int G = c & ~15, u = (c >> 2) & 3;      // c = G + 4u
        float* o = out + r * 512 + G + u;       // perm(c+j) = G + 4j + u
        o[0]  = tf32r(v.x);
        o[4]  = tf32r(v.y);
        o[8]  = tf32r(v.z);
        o[12] = tf32r(v.w);
    }
}

// ---------------- weight prep: round + transpose [K,Nh]->[Nh,K] + k-permute ----------------
__global__ void prep_w_kernel(const float* __restrict__ W, float* __restrict__ Wt,
                              int K, int Nh) {
    __shared__ float tile[32][33];
    int k0 = blockIdx.y * 32, n0 = blockIdx.x * 32;
    int tx = threadIdx.x, ty = threadIdx.y;     // block (32,8)
#pragma unroll
    for (int i = 0; i < 4; i++)
        tile[ty + i * 8][tx] = tf32r(W[(long)(k0 + ty + i * 8) * Nh + n0 + tx]);
    __syncthreads();
#pragma unroll
    for (int i = 0; i < 4; i++) {
        int n = n0 + ty + i * 8;
        int k = k0 + tx;
        Wt[(long)n * K + permk(k)] = tile[tx][ty + i * 8];
    }
}

// ---------------- CSR build ----------------
__global__ void hist_kernel(const int* __restrict__ dst, int* __restrict__ cnt, int E) {
    int e = blockIdx.x * blockDim.x + threadIdx.x;
    if (e < E) atomicAdd(&cnt[dst[e]], 1);
}

__global__ void scan_kernel(const int* __restrict__ cnt, int* __restrict__ rowptr, int n) {
    __shared__ int smem[1024];
    __shared__ int carry;
    int tid = threadIdx.x;
    if (tid == 0) { carry = 0; rowptr[0] = 0; }
    __syncthreads();
    for (int base = 0; base < n; base += 1024) {
        int c = carry;
        __syncthreads();
        int i = base + tid;
        int v = (i < n) ? cnt[i] : 0;
        smem[tid] = v;
        __syncthreads();
        for (int off = 1; off < 1024; off <<= 1) {
            int t = (tid >= off) ? smem[tid - off] : 0;
            __syncthreads();
            smem[tid] += t;
            __syncthreads();
        }
        if (i < n) rowptr[i + 1] = smem[tid] + c;
        __syncthreads();
        if (tid == 0) carry = c + smem[1023];
        __syncthreads();
    }
}

__global__ void scatter_kernel(const int* __restrict__ src, const int* __restrict__ dst,
                               const int* __restrict__ rowptr, int* __restrict__ cursor,
                               int* __restrict__ csrsrc, int E) {
    int e = blockIdx.x * blockDim.x + threadIdx.x;
    if (e < E) {
        int d = dst[e];
        int pos = rowptr[d] + atomicAdd(&cursor[d], 1);
        csrsrc[pos] = src[e];
    }
}

// ---------------- TF32 tensor-core GEMM ----------------
// C[M, 2*Nh] = A[M,K] @ [Bl|Br]^T-packed; A is [M,K] k-permuted, B is [Nh,K] k-permuted.
// BM=128, BN=128, BK=32; 256 threads = 8 warps (4m x 2n), warp tile 32x64.
// 3-stage cp.async pipeline, 1 __syncthreads per tile, LDS.128 fragment loads.
#define BM 128
#define BN 128
#define BK 32
#define ST 48                        // smem row stride (words); 48 % 32 == 16 -> conflict-free
#define STAGE_WORDS (2 * 128 * ST)   // A(128 rows) + B(128 rows) = 12288
#define NSTAGE 3
#define SMEM_BYTES (NSTAGE * STAGE_WORDS * 4)   // 147456

__device__ __forceinline__ void cp16(float* dst, const float* src, bool p) {
    uint32_t d = (uint32_t)__cvta_generic_to_shared(dst);
    int sz = p ? 16 : 0;
    asm volatile("cp.async.cg.shared.global [%0], [%1], 16, %2;\n" :: "r"(d), "l"(src), "r"(sz));
}

__device__ __forceinline__ void mma_tf32(float* d, uint32_t a0, uint32_t a1, uint32_t a2,
                                         uint32_t a3, uint32_t b0, uint32_t b1) {
    asm volatile(
        "mma.sync.aligned.m16n8k8.row.col.f32.tf32.tf32.f32 "
        "{%0,%1,%2,%3}, {%4,%5,%6,%7}, {%8,%9}, {%0,%1,%2,%3};\n"
        : "+f"(d[0]), "+f"(d[1]), "+f"(d[2]), "+f"(d[3])
        : "r"(a0), "r"(a1), "r"(a2), "r"(a3), "r"(b0), "r"(b1));
}

__global__ __launch_bounds__(256) void gemm_tc3_kernel(
        const float* __restrict__ A, const float* __restrict__ Bl,
        const float* __restrict__ Br, float* __restrict__ C,
        int M, int Nh, int K) {
    extern __shared__ float smem[];
    const int Ntot = 2 * Nh;

    int tid  = threadIdx.x;
    int warp = tid >> 5, lane = tid & 31;
    int g = lane >> 2, t = lane & 3;
    int mb = blockIdx.y * BM;
    int nb = blockIdx.x * BN;
    const float* B = (nb < Nh) ? Bl : Br;          // [Nh,K] row-major, k-permuted
    int ncol = (nb < Nh) ? nb : nb - Nh;
    int wm = (warp & 3) * 32, wn = (warp >> 2) * 64;

    float c[2][8][4];
#pragma unroll
    for (int i = 0; i < 2; i++)
#pragma unroll
        for (int j = 0; j < 8; j++)
#pragma unroll
            for (int r = 0; r < 4; r++) c[i][j][r] = 0.f;

    int l_row = tid >> 3;            // 0..31 (x4 -> 128 rows)
    int l_kq  = (tid & 7) * 4;       // k word offset

    auto load_tile = [&](int stg, int k0) {
        float* As = smem + stg * STAGE_WORDS;
        float* Bs = As + 128 * ST;
#pragma unroll
        for (int i = 0; i < 4; i++) {
            int row = l_row + i * 32;
            cp16(&As[row * ST + l_kq], A + (long)(mb + row) * K + k0 + l_kq, (mb + row) < M);
        }
#pragma unroll
        for (int i = 0; i < 4; i++) {
            int row = l_row + i * 32;
            cp16(&Bs[row * ST + l_kq], B + (long)(ncol + row) * K + k0 + l_kq, true);
        }
        asm volatile("cp.async.commit_group;\n" ::);
    };

    int nt = K / BK;
    load_tile(0, 0);
    if (nt > 1) load_tile(1, BK); else asm volatile("cp.async.commit_group;\n" ::);

    for (int kt = 0; kt < nt; kt++) {
        asm volatile("cp.async.wait_group 1;\n" ::);
        __syncthreads();
        // issue load for kt+2 (buffer free after the barrier)
        if (kt + 2 < nt) load_tile((kt + 2) % NSTAGE, (kt + 2) * BK);
        else asm volatile("cp.async.commit_group;\n" ::);

        const float* As = smem + (kt % NSTAGE) * STAGE_WORDS;
        const float* Bs = As + 128 * ST;
#pragma unroll
        for (int ch = 0; ch < 2; ch++) {            // two 16-k chunks
            int ko = ch * 16 + 4 * t;
            uint4 alo[2], ahi[2], bv[8];
#pragma unroll
            for (int im = 0; im < 2; im++) {
                alo[im] = *reinterpret_cast<const uint4*>(&As[(wm + im * 16 + g) * ST + ko]);
                ahi[im] = *reinterpret_cast<const uint4*>(&As[(wm + im * 16 + 8 + g) * ST + ko]);
            }
#pragma unroll
            for (int jn = 0; jn < 8; jn++)
                bv[jn] = *reinterpret_cast<const uint4*>(&Bs[(wn + jn * 8 + g) * ST + ko]);
            // ks = 0 uses (v0, v1) = k {t, t+4}; ks = 1 uses (v2, v3) = k {t+8, t+12}
#pragma unroll
            for (int im = 0; im < 2; im++)
#pragma unroll
                for (int jn = 0; jn < 8; jn++)
                    mma_tf32(c[im][jn], alo[im].x, ahi[im].x, alo[im].y, ahi[im].y,
                             bv[jn].x, bv[jn].y);
#pragma unroll
            for (int im = 0; im < 2; im++)
#pragma unroll
                for (int jn = 0; jn < 8; jn++)
                    mma_tf32(c[im][jn], alo[im].z, ahi[im].z, alo[im].w, ahi[im].w,
                             bv[jn].z, bv[jn].w);
        }
        __syncthreads();
    }

#pragma unroll
    for (int im = 0; im < 2; im++) {
#pragma unroll
        for (int jn = 0; jn < 8; jn++) {
            int col = nb + wn + jn * 8 + t * 2;
            int row0 = mb + wm + im * 16 + g;
            if (row0 < M)
                *reinterpret_cast<float2*>(&C[(long)row0 * Ntot + col]) =
                    make_float2(c[im][jn][0], c[im][jn][1]);
            int row1 = row0 + 8;
            if (row1 < M)
                *reinterpret_cast<float2*>(&C[(long)row1 * Ntot + col]) =
                    make_float2(c[im][jn][2], c[im][jn][3]);
        }
    }
}

// ---------------- fused GATv2 aggregation ----------------
template <int VPT>
__device__ __forceinline__ void vload(float* x, const float* p);
template <>
__device__ __forceinline__ void vload<4>(float* x, const float* p) {
    float4 v = *reinterpret_cast<const float4*>(p);
    x[0] = v.x; x[1] = v.y; x[2] = v.z; x[3] = v.w;
}
template <>
__device__ __forceinline__ void vload<2>(float* x, const float* p) {
    float2 v = *reinterpret_cast<const float2*>(p);
    x[0] = v.x; x[1] = v.y;
}

// PERM: write output with k-permuted columns (when feeding the next GEMM)
template <int D, bool PERM>
__global__ void gat_agg_kernel(const float* __restrict__ proj,
                               const float* __restrict__ attn, const float* __restrict__ bias,
                               const int* __restrict__ rowptr, const int* __restrict__ csrsrc,
                               float* __restrict__ hout, int stride) {
    constexpr int VPT = D / 32;
    int v = blockIdx.x;
    int h = threadIdx.x >> 5;
    int lane = threadIdx.x & 31;
    int dbase = lane * VPT;
    int fdoff = stride >> 1;

    float fdv[VPT], at[VPT], acc[VPT];
    vload<VPT>(fdv, proj + (long)v * stride + fdoff + h * D + dbase);
    vload<VPT>(at,  attn + h * D + dbase);
#pragma unroll
    for (int j = 0; j < VPT; j++) acc[j] = 0.f;

    float m = -INFINITY, s = 0.f;

    int e0 = rowptr[v], e1 = rowptr[v + 1];
    if (e0 < e1) {
        int u = csrsrc[e0];
        float x[VPT];
        vload<VPT>(x, proj + (long)u * stride + h * D + dbase);
        for (int e = e0; e < e1; e++) {
            float xn[VPT];
            int en = (e + 1 < e1) ? e + 1 : e;
            int un = csrsrc[en];
            vload<VPT>(xn, proj + (long)un * stride + h * D + dbase);

            float p = 0.f;
#pragma unroll
            for (int j = 0; j < VPT; j++) {
                float tt = x[j] + fdv[j];
                tt = fmaxf(tt, 0.2f * tt);
                p = fmaf(tt, at[j], p);
            }
#pragma unroll
            for (int off = 16; off; off >>= 1)
                p += __shfl_xor_sync(0xffffffffu, p, off);

            float mn = fmaxf(m, p);
            float corr = __expf(m - mn);
            float w = __expf(p - mn);
            s = s * corr + w;
#pragma unroll
            for (int j = 0; j < VPT; j++)
                acc[j] = fmaf(acc[j], corr, w * x[j]);
            m = mn;
#pragma unroll
            for (int j = 0; j < VPT; j++) x[j] = xn[j];
        }
    }

    __shared__ float hm[HH][D];
    float inv_s = (e1 > e0) ? (1.f / s) : 0.f;
#pragma unroll
    for (int j = 0; j < VPT; j++)
        hm[h][dbase + j] = fmaf(acc[j], inv_s, bias[h * D + dbase + j]);
    __syncthreads();
    for (int d = threadIdx.x; d < D; d += blockDim.x) {
        float mv = 0.25f * (hm[0][d] + hm[1][d] + hm[2][d] + hm[3][d]);
        mv = fmaxf(mv, 0.01f * mv);
        int od = PERM ? permk(d) : d;
        hout[(long)v * D + od] = tf32r(mv);
    }
}

// ---------------- final mean over nodes ----------------
__global__ void final_mean_kernel(const float* __restrict__ hin, float* __restrict__ out, int n) {
    int d = threadIdx.x;  // blockDim = 64
    float sum = 0.f;
    for (int r = blockIdx.x; r < n; r += gridDim.x)
        sum += hin[(long)r * 64 + d];
    atomicAdd(&out[d], sum * (1.0f / (float)NN));
}

// ---------------- launch ----------------
extern "C" void kernel_launch(void* const* d_in, const int* in_sizes, int n_in,
                              void* d_out, int out_size) {
    const float* n_feat = (const float*)d_in[0];
    const int*   src    = (const int*)d_in[1];
    const int*   dst    = (const int*)d_in[2];
    const float* Wl0 = (const float*)d_in[3];
    const float* Wr0 = (const float*)d_in[4];
    const float* attn0 = (const float*)d_in[5];
    const float* b0 = (const float*)d_in[6];
    const float* Wl1 = (const float*)d_in[7];
    const float* Wr1 = (const float*)d_in[8];
    const float* attn1 = (const float*)d_in[9];
    const float* b1 = (const float*)d_in[10];
    const float* Wl2 = (const float*)d_in[11];
    const float* Wr2 = (const float*)d_in[12];
    const float* attn2 = (const float*)d_in[13];
    const float* b2 = (const float*)d_in[14];
    float* out = (float*)d_out;

    float *proj, *A0, *h1, *h2, *wbuf;
    int *cnt, *cursor, *rowptr, *csrsrc;
    cudaGetSymbolAddress((void**)&proj, g_proj);
    cudaGetSymbolAddress((void**)&A0, g_A0);
    cudaGetSymbolAddress((void**)&h1, g_h1);
    cudaGetSymbolAddress((void**)&h2, g_h2);
    cudaGetSymbolAddress((void**)&wbuf, g_wbuf);
    cudaGetSymbolAddress((void**)&cnt, g_cnt);
    cudaGetSymbolAddress((void**)&cursor, g_cursor);
    cudaGetSymbolAddress((void**)&rowptr, g_rowptr);
    cudaGetSymbolAddress((void**)&csrsrc, g_csrsrc);

    cudaFuncSetAttribute(gemm_tc3_kernel,
                         cudaFuncAttributeMaxDynamicSharedMemorySize, SMEM_BYTES);

    const int N = NN, E = EE;

    // CSR build
    cudaMemsetAsync(cnt, 0, N * sizeof(int));
    cudaMemsetAsync(cursor, 0, N * sizeof(int));
    hist_kernel<<<(E + 255) / 256, 256>>>(dst, cnt, E);
    scan_kernel<<<1, 1024>>>(cnt, rowptr, N);
    scatter_kernel<<<(E + 255) / 256, 256>>>(src, dst, rowptr, cursor, csrsrc, E);

    // A0 prep (round + k-permute)
    prep_a0_kernel<<<(NN * 512 / 4 + 255) / 256, 256>>>(n_feat, A0, NN * 512);

    // weight prep: round + transpose [K,Nh]->[Nh,K] + k-permute
    dim3 wtb(32, 8);
    prep_w_kernel<<<dim3(512 / 32, 512 / 32), wtb>>>(Wl0, wbuf + OFF_WL0, 512, 512);
    prep_w_kernel<<<dim3(512 / 32, 512 / 32), wtb>>>(Wr0, wbuf + OFF_WR0, 512, 512);
    prep_w_kernel<<<dim3(512 / 32, 128 / 32), wtb>>>(Wl1, wbuf + OFF_WL1, 128, 512);
    prep_w_kernel<<<dim3(512 / 32, 128 / 32), wtb>>>(Wr1, wbuf + OFF_WR1, 128, 512);
    prep_w_kernel<<<dim3(256 / 32, 128 / 32), wtb>>>(Wl2, wbuf + OFF_WL2, 128, 256);
    prep_w_kernel<<<dim3(256 / 32, 128 / 32), wtb>>>(Wr2, wbuf + OFF_WR2, 128, 256);

    dim3 tb(256);
    int mblk = (N + BM - 1) / BM;

    // ---- layer 0: 512 -> H x 128 ----
    gemm_tc3_kernel<<<dim3(1024 / BN, mblk), tb, SMEM_BYTES>>>(
        A0, wbuf + OFF_WL0, wbuf + OFF_WR0, proj, N, 512, 512);
    gat_agg_kernel<128, true><<<N, 128>>>(proj, attn0, b0, rowptr, csrsrc, h1, 1024);

    // ---- layer 1: 128 -> H x 128 ----
    gemm_tc3_kernel<<<dim3(1024 / BN, mblk), tb, SMEM_BYTES>>>(
        h1, wbuf + OFF_WL1, wbuf + OFF_WR1, proj, N, 512, 128);
    gat_agg_kernel<128, true><<<N, 128>>>(proj, attn1, b1, rowptr, csrsrc, h2, 1024);

    // ---- layer 2 (output): 128 -> H x 64 ----
    gemm_tc3_kernel<<<dim3(512 / BN, mblk), tb, SMEM_BYTES>>>(
        h2, wbuf + OFF_WL2, wbuf + OFF_WR2, proj, N, 256, 128);
    gat_agg_kernel<64, false><<<N, 128>>>(proj, attn2, b2, rowptr, csrsrc, h1, 512);

    // ---- readout ----
    cudaMemsetAsync(out, 0, 64 * sizeof(float));
    final_mean_kernel<<<256, 64>>>(h1, out, N);
}

// round 6
// speedup vs baseline: 1.2610x; 1.2610x over previous
#include <cuda_runtime.h>
#include <cuda_fp16.h>
#include <math.h>
#include <stdint.h>

// Problem constants
#define NN   20000
#define EE   320000
#define HH   4

// ---------------- scratch (static __device__, no allocs) ----------------
__device__ __align__(16) __half g_proj[NN * 1024];  // [fs | fd] fp16
__device__ __align__(16) __half g_A0[NN * 512];     // fp16 n_feat
__device__ __align__(16) __half g_h1[NN * 128];     // hidden outputs fp16
__device__ __align__(16) __half g_h2[NN * 128];
__device__ __align__(16) __half g_wbuf[720896];     // fp16 weights, transposed [Nh,K]
__device__ float g_hf[NN * 64];                     // final layer output fp32
__device__ int   g_cnt[NN];
__device__ int   g_cursor[NN];
__device__ int   g_rowptr[NN + 1];
__device__ int   g_csrsrc[EE];

#define OFF_WL0 0
#define OFF_WR0 262144
#define OFF_WL1 524288
#define OFF_WR1 589824
#define OFF_WL2 655360
#define OFF_WR2 688128

// ---------------- A0 prep: fp32 -> fp16 ----------------
__global__ void prep_a0_kernel(const float* __restrict__ in, __half* __restrict__ out, int n) {
    int i = (blockIdx.x * blockDim.x + threadIdx.x) * 4;
    if (i < n) {
        float4 v = *reinterpret_cast<const float4*>(in + i);
        __half2 h01 = __floats2half2_rn(v.x, v.y);
        __half2 h23 = __floats2half2_rn(v.z, v.w);
        uint2 packed;
        packed.x = *reinterpret_cast<uint32_t*>(&h01);
        packed.y = *reinterpret_cast<uint32_t*>(&h23);
        *reinterpret_cast<uint2*>(out + i) = packed;
    }
}

// ---------------- weight prep: transpose [K,Nh]->[Nh,K] + fp16 ----------------
__global__ void prep_w_kernel(const float* __restrict__ W, __half* __restrict__ Wt,
                              int K, int Nh) {
    __shared__ float tile[32][33];
    int k0 = blockIdx.y * 32, n0 = blockIdx.x * 32;
    int tx = threadIdx.x, ty = threadIdx.y;     // block (32,8)
#pragma unroll
    for (int i = 0; i < 4; i++)
        tile[ty + i * 8][tx] = W[(long)(k0 + ty + i * 8) * Nh + n0 + tx];
    __syncthreads();
#pragma unroll
    for (int i = 0; i < 4; i++) {
        int n = n0 + ty + i * 8;
        int k = k0 + tx;
        Wt[(long)n * K + k] = __float2half_rn(tile[tx][ty + i * 8]);
    }
}

// ---------------- CSR build ----------------
__global__ void hist_kernel(const int* __restrict__ dst, int* __restrict__ cnt, int E) {
    int e = blockIdx.x * blockDim.x + threadIdx.x;
    if (e < E) atomicAdd(&cnt[dst[e]], 1);
}

__global__ void scan_kernel(const int* __restrict__ cnt, int* __restrict__ rowptr, int n) {
    __shared__ int smem[1024];
    __shared__ int carry;
    int tid = threadIdx.x;
    if (tid == 0) { carry = 0; rowptr[0] = 0; }
    __syncthreads();
    for (int base = 0; base < n; base += 1024) {
        int c = carry;
        __syncthreads();
        int i = base + tid;
        int v = (i < n) ? cnt[i] : 0;
        smem[tid] = v;
        __syncthreads();
        for (int off = 1; off < 1024; off <<= 1) {
            int t = (tid >= off) ? smem[tid - off] : 0;
            __syncthreads();
            smem[tid] += t;
            __syncthreads();
        }
        if (i < n) rowptr[i + 1] = smem[tid] + c;
        __syncthreads();
        if (tid == 0) carry = c + smem[1023];
        __syncthreads();
    }
}

__global__ void scatter_kernel(const int* __restrict__ src, const int* __restrict__ dst,
                               const int* __restrict__ rowptr, int* __restrict__ cursor,
                               int* __restrict__ csrsrc, int E) {
    int e = blockIdx.x * blockDim.x + threadIdx.x;
    if (e < E) {
        int d = dst[e];
        int pos = rowptr[d] + atomicAdd(&cursor[d], 1);
        csrsrc[pos] = src[e];
    }
}

// ---------------- FP16 tensor-core GEMM ----------------
// C[M, 2*Nh] (fp16) = A[M,K] @ [Bl|Br] with B stored as [Nh,K] (transposed).
// BM=128, BN=128, BK=32 halves. 256 threads = 8 warps (4m x 2n), warp tile 32x64.
// 3-stage cp.async, 1 barrier/tile, ldmatrix.x4 frag loads, XOR-swizzled smem.
#define BM 128
#define BN 128
#define BKH 32
#define STAGE_BYTES 16384          // A 128x4x16B + B 128x4x16B
#define NSTAGE 3
#define SMEM_BYTES (NSTAGE * STAGE_BYTES)  // 49152

__device__ __forceinline__ void cp16s(uint32_t dst, const void* src, bool p) {
    int sz = p ? 16 : 0;
    asm volatile("cp.async.cg.shared.global [%0], [%1], 16, %2;\n" :: "r"(dst), "l"(src), "r"(sz));
}

__device__ __forceinline__ void ldmx4(uint32_t addr, uint32_t& r0, uint32_t& r1,
                                      uint32_t& r2, uint32_t& r3) {
    asm volatile("ldmatrix.sync.aligned.m8n8.x4.shared.b16 {%0,%1,%2,%3}, [%4];\n"
                 : "=r"(r0), "=r"(r1), "=r"(r2), "=r"(r3) : "r"(addr));
}

__device__ __forceinline__ void mma_f16(float* d, uint32_t a0, uint32_t a1, uint32_t a2,
                                        uint32_t a3, uint32_t b0, uint32_t b1) {
    asm volatile(
        "mma.sync.aligned.m16n8k16.row.col.f32.f16.f16.f32 "
        "{%0,%1,%2,%3}, {%4,%5,%6,%7}, {%8,%9}, {%0,%1,%2,%3};\n"
        : "+f"(d[0]), "+f"(d[1]), "+f"(d[2]), "+f"(d[3])
        : "r"(a0), "r"(a1), "r"(a2), "r"(a3), "r"(b0), "r"(b1));
}

__global__ __launch_bounds__(256) void gemm_f16_kernel(
        const __half* __restrict__ A, const __half* __restrict__ Bl,
        const __half* __restrict__ Br, __half* __restrict__ C,
        int M, int Nh, int K) {
    extern __shared__ __align__(16) uint4 smem_u4[];
    uint32_t smem0 = (uint32_t)__cvta_generic_to_shared(smem_u4);
    const int Ntot = 2 * Nh;

    int tid  = threadIdx.x;
    int warp = tid >> 5, lane = tid & 31;
    int g = lane >> 2, t = lane & 3;
    int mb = blockIdx.y * BM;
    int nb = blockIdx.x * BN;
    const __half* B = (nb < Nh) ? Bl : Br;          // [Nh,K]
    int ncol = (nb < Nh) ? nb : nb - Nh;
    int wm = (warp & 3) * 32, wn = (warp >> 2) * 64;

    float c[2][8][4];
#pragma unroll
    for (int i = 0; i < 2; i++)
#pragma unroll
        for (int j = 0; j < 8; j++)
#pragma unroll
            for (int r = 0; r < 4; r++) c[i][j][r] = 0.f;

    // loader: 256 threads; row = tid/4 (0..63, +64), chunk = tid%4 (16B units)
    int l_row = tid >> 2;
    int l_ck  = tid & 3;

    auto load_tile = [&](int stg, int k0) {
        uint32_t Ab = smem0 + stg * STAGE_BYTES;
        uint32_t Bb = Ab + 8192;
#pragma unroll
        for (int i = 0; i < 2; i++) {
            int r = l_row + i * 64;
            int p = (l_ck ^ ((r >> 1) & 3));
            cp16s(Ab + (r * 4 + p) * 16, A + (long)(mb + r) * K + k0 + l_ck * 8, (mb + r) < M);
        }
#pragma unroll
        for (int i = 0; i < 2; i++) {
            int r = l_row + i * 64;
            int p = (l_ck ^ ((r >> 1) & 3));
            cp16s(Bb + (r * 4 + p) * 16, B + (long)(ncol + r) * K + k0 + l_ck * 8, true);
        }
        asm volatile("cp.async.commit_group;\n" ::);
    };

    // frag address precompute: lane -> row base + (l&15), chunk low bit (l>>4)
    int lr = lane & 15, lc = lane >> 4;
    int rowA[2], rswA[2], rowB[4], rswB[4];
#pragma unroll
    for (int im = 0; im < 2; im++) {
        rowA[im] = wm + im * 16 + lr;
        rswA[im] = (rowA[im] >> 1) & 3;
    }
#pragma unroll
    for (int jg = 0; jg < 4; jg++) {
        rowB[jg] = wn + jg * 16 + lr;
        rswB[jg] = (rowB[jg] >> 1) & 3;
    }

    int nt = K / BKH;
    load_tile(0, 0);
    if (nt > 1) load_tile(1, BKH); else asm volatile("cp.async.commit_group;\n" ::);

    for (int kt = 0; kt < nt; kt++) {
        asm volatile("cp.async.wait_group 1;\n" ::);
        __syncthreads();
        if (kt + 2 < nt) load_tile((kt + 2) % NSTAGE, (kt + 2) * BKH);
        else asm volatile("cp.async.commit_group;\n" ::);

        uint32_t Ab = smem0 + (kt % NSTAGE) * STAGE_BYTES;
        uint32_t Bb = Ab + 8192;
#pragma unroll
        for (int ks = 0; ks < 2; ks++) {
            uint32_t a[2][4];
#pragma unroll
            for (int im = 0; im < 2; im++) {
                int p = ((2 * ks + lc) ^ rswA[im]) & 3;
                ldmx4(Ab + rowA[im] * 64 + p * 16, a[im][0], a[im][1], a[im][2], a[im][3]);
            }
#pragma unroll
            for (int jg = 0; jg < 4; jg++) {
                int p = ((2 * ks + lc) ^ rswB[jg]) & 3;
                uint32_t r0, r1, r2, r3;
                ldmx4(Bb + rowB[jg] * 64 + p * 16, r0, r1, r2, r3);
#pragma unroll
                for (int im = 0; im < 2; im++) {
                    mma_f16(c[im][jg * 2 + 0], a[im][0], a[im][1], a[im][2], a[im][3], r0, r2);
                    mma_f16(c[im][jg * 2 + 1], a[im][0], a[im][1], a[im][2], a[im][3], r1, r3);
                }
            }
        }
    }

    __syncthreads();
#pragma unroll
    for (int im = 0; im < 2; im++) {
#pragma unroll
        for (int jn = 0; jn < 8; jn++) {
            int col = nb + wn + jn * 8 + t * 2;
            int row0 = mb + wm + im * 16 + g;
            if (row0 < M)
                *reinterpret_cast<__half2*>(&C[(long)row0 * Ntot + col]) =
                    __floats2half2_rn(c[im][jn][0], c[im][jn][1]);
            int row1 = row0 + 8;
            if (row1 < M)
                *reinterpret_cast<__half2*>(&C[(long)row1 * Ntot + col]) =
                    __floats2half2_rn(c[im][jn][2], c[im][jn][3]);
        }
    }
}

// ---------------- fused GATv2 aggregation (fp16 inputs, fp32 math) ----------------
template <int VPT>
__device__ __forceinline__ void vloadh(float* x, const __half* p);
template <>
__device__ __forceinline__ void vloadh<4>(float* x, const __half* p) {
    uint2 raw = *reinterpret_cast<const uint2*>(p);
    float2 f0 = __half22float2(*reinterpret_cast<__half2*>(&raw.x));
    float2 f1 = __half22float2(*reinterpret_cast<__half2*>(&raw.y));
    x[0] = f0.x; x[1] = f0.y; x[2] = f1.x; x[3] = f1.y;
}
template <>
__device__ __forceinline__ void vloadh<2>(float* x, const __half* p) {
    uint32_t raw = *reinterpret_cast<const uint32_t*>(p);
    float2 f0 = __half22float2(*reinterpret_cast<__half2*>(&raw));
    x[0] = f0.x; x[1] = f0.y;
}

__device__ __forceinline__ void storev(__half* p, float v) { *p = __float2half_rn(v); }
__device__ __forceinline__ void storev(float* p, float v) { *p = v; }

template <int D, typename OutT>
__global__ void gat_agg_kernel(const __half* __restrict__ proj,
                               const float* __restrict__ attn, const float* __restrict__ bias,
                               const int* __restrict__ rowptr, const int* __restrict__ csrsrc,
                               OutT* __restrict__ hout, int stride) {
    constexpr int VPT = D / 32;
    int v = blockIdx.x;
    int h = threadIdx.x >> 5;
    int lane = threadIdx.x & 31;
    int dbase = lane * VPT;
    int fdoff = stride >> 1;

    float fdv[VPT], at[VPT], acc[VPT];
    vloadh<VPT>(fdv, proj + (long)v * stride + fdoff + h * D + dbase);
#pragma unroll
    for (int j = 0; j < VPT; j++) {
        at[j] = attn[h * D + dbase + j];
        acc[j] = 0.f;
    }

    float m = -INFINITY, s = 0.f;

    int e0 = rowptr[v], e1 = rowptr[v + 1];
    if (e0 < e1) {
        int u = csrsrc[e0];
        float x[VPT];
        vloadh<VPT>(x, proj + (long)u * stride + h * D + dbase);
        for (int e = e0; e < e1; e++) {
            float xn[VPT];
            int en = (e + 1 < e1) ? e + 1 : e;
            int un = csrsrc[en];
            vloadh<VPT>(xn, proj + (long)un * stride + h * D + dbase);

            float p = 0.f;
#pragma unroll
            for (int j = 0; j < VPT; j++) {
                float tt = x[j] + fdv[j];
                tt = fmaxf(tt, 0.2f * tt);     // GATv2 internal leaky_relu
                p = fmaf(tt, at[j], p);
            }
#pragma unroll
            for (int off = 16; off; off >>= 1)
                p += __shfl_xor_sync(0xffffffffu, p, off);

            float mn = fmaxf(m, p);
            float corr = __expf(m - mn);       // 0 on first edge
            float w = __expf(p - mn);
            s = s * corr + w;
#pragma unroll
            for (int j = 0; j < VPT; j++)
                acc[j] = fmaf(acc[j], corr, w * x[j]);
            m = mn;
#pragma unroll
            for (int j = 0; j < VPT; j++) x[j] = xn[j];
        }
    }

    __shared__ float hm[HH][D];
    float inv_s = (e1 > e0) ? (1.f / s) : 0.f;
#pragma unroll
    for (int j = 0; j < VPT; j++)
        hm[h][dbase + j] = fmaf(acc[j], inv_s, bias[h * D + dbase + j]);
    __syncthreads();
    for (int d = threadIdx.x; d < D; d += blockDim.x) {
        float mv = 0.25f * (hm[0][d] + hm[1][d] + hm[2][d] + hm[3][d]);
        mv = fmaxf(mv, 0.01f * mv);            // ACT leaky_relu
        storev(&hout[(long)v * D + d], mv);
    }
}

// ---------------- final mean over nodes ----------------
__global__ void final_mean_kernel(const float* __restrict__ hin, float* __restrict__ out, int n) {
    int d = threadIdx.x;  // blockDim = 64
    float sum = 0.f;
    for (int r = blockIdx.x; r < n; r += gridDim.x)
        sum += hin[(long)r * 64 + d];
    atomicAdd(&out[d], sum * (1.0f / (float)NN));
}

// ---------------- launch ----------------
extern "C" void kernel_launch(void* const* d_in, const int* in_sizes, int n_in,
                              void* d_out, int out_size) {
    const float* n_feat = (const float*)d_in[0];
    const int*   src    = (const int*)d_in[1];
    const int*   dst    = (const int*)d_in[2];
    const float* Wl0 = (const float*)d_in[3];
    const float* Wr0 = (const float*)d_in[4];
    const float* attn0 = (const float*)d_in[5];
    const float* b0 = (const float*)d_in[6];
    const float* Wl1 = (const float*)d_in[7];
    const float* Wr1 = (const float*)d_in[8];
    const float* attn1 = (const float*)d_in[9];
    const float* b1 = (const float*)d_in[10];
    const float* Wl2 = (const float*)d_in[11];
    const float* Wr2 = (const float*)d_in[12];
    const float* attn2 = (const float*)d_in[13];
    const float* b2 = (const float*)d_in[14];
    float* out = (float*)d_out;

    __half *proj, *A0, *h1, *h2, *wbuf;
    float *hf;
    int *cnt, *cursor, *rowptr, *csrsrc;
    cudaGetSymbolAddress((void**)&proj, g_proj);
    cudaGetSymbolAddress((void**)&A0, g_A0);
    cudaGetSymbolAddress((void**)&h1, g_h1);
    cudaGetSymbolAddress((void**)&h2, g_h2);
    cudaGetSymbolAddress((void**)&wbuf, g_wbuf);
    cudaGetSymbolAddress((void**)&hf, g_hf);
    cudaGetSymbolAddress((void**)&cnt, g_cnt);
    cudaGetSymbolAddress((void**)&cursor, g_cursor);
    cudaGetSymbolAddress((void**)&rowptr, g_rowptr);
    cudaGetSymbolAddress((void**)&csrsrc, g_csrsrc);

    cudaFuncSetAttribute(gemm_f16_kernel,
                         cudaFuncAttributeMaxDynamicSharedMemorySize, SMEM_BYTES);

    const int N = NN, E = EE;

    // CSR build
    cudaMemsetAsync(cnt, 0, N * sizeof(int));
    cudaMemsetAsync(cursor, 0, N * sizeof(int));
    hist_kernel<<<(E + 255) / 256, 256>>>(dst, cnt, E);
    scan_kernel<<<1, 1024>>>(cnt, rowptr, N);
    scatter_kernel<<<(E + 255) / 256, 256>>>(src, dst, rowptr, cursor, csrsrc, E);

    // fp16 prep
    prep_a0_kernel<<<(NN * 512 / 4 + 255) / 256, 256>>>(n_feat, A0, NN * 512);
    dim3 wtb(32, 8);
    prep_w_kernel<<<dim3(512 / 32, 512 / 32), wtb>>>(Wl0, wbuf + OFF_WL0, 512, 512);
    prep_w_kernel<<<dim3(512 / 32, 512 / 32), wtb>>>(Wr0, wbuf + OFF_WR0, 512, 512);
    prep_w_kernel<<<dim3(512 / 32, 128 / 32), wtb>>>(Wl1, wbuf + OFF_WL1, 128, 512);
    prep_w_kernel<<<dim3(512 / 32, 128 / 32), wtb>>>(Wr1, wbuf + OFF_WR1, 128, 512);
    prep_w_kernel<<<dim3(256 / 32, 128 / 32), wtb>>>(Wl2, wbuf + OFF_WL2, 128, 256);
    prep_w_kernel<<<dim3(256 / 32, 128 / 32), wtb>>>(Wr2, wbuf + OFF_WR2, 128, 256);

    dim3 tb(256);
    int mblk = (N + BM - 1) / BM;

    // ---- layer 0: 512 -> H x 128 ----
    gemm_f16_kernel<<<dim3(1024 / BN, mblk), tb, SMEM_BYTES>>>(
        A0, wbuf + OFF_WL0, wbuf + OFF_WR0, proj, N, 512, 512);
    gat_agg_kernel<128, __half><<<N, 128>>>(proj, attn0, b0, rowptr, csrsrc, h1, 1024);

    // ---- layer 1: 128 -> H x 128 ----
    gemm_f16_kernel<<<dim3(1024 / BN, mblk), tb, SMEM_BYTES>>>(
        h1, wbuf + OFF_WL1, wbuf + OFF_WR1, proj, N, 512, 128);
    gat_agg_kernel<128, __half><<<N, 128>>>(proj, attn1, b1, rowptr, csrsrc, h2, 1024);

    // ---- layer 2 (output): 128 -> H x 64 ----
    gemm_f16_kernel<<<dim3(512 / BN, mblk), tb, SMEM_BYTES>>>(
        h2, wbuf + OFF_WL2, wbuf + OFF_WR2, proj, N, 256, 128);
    gat_agg_kernel<64, float><<<N, 128>>>(proj, attn2, b2, rowptr, csrsrc, hf, 512);

    // ---- readout ----
    cudaMemsetAsync(out, 0, 64 * sizeof(float));
    final_mean_kernel<<<256, 64>>>(hf, out, N);
}